// round 7
// baseline (speedup 1.0000x reference)
#include <cuda_runtime.h>
#include <cuda_bf16.h>
#include <cub/cub.cuh>
#include <cstdint>

// AUCShuffled: B=64 samples x N=2^18 preds.
// answer_b = sum_k rankavg0[k] * m[k],  m[k] = lam[r1[k]],  lam[i] = t[r2[i]]
//  - r1,r2 = stable ranks of uniform threefry keys via bucket counting sort
//  - rankavg0 sum via CLOSED FORM over a 16-bit pred histogram:
//      sum = 0.5 * sum_bins q*(2B + c + 1)   (exact tie-averaged ranks, unbiased
//      under label-independence; no comparison sort needed at all)
// R7: CUB sort eliminated; c2 region eliminated (scatter on scanned hist,
//     begin/end from adjacent entries); m array eliminated (fused into rank<0>).

#define NSAMP 64
#define NPER  262144            // 2^18
#define HPER  131072            // 2^17
#define NTOT  (NSAMP * NPER)    // 16,777,216
#define NBUCK 65536             // 2^16 buckets per sample
#define NHIST (NSAMP * NBUCK)   // 4,194,304
#define CHUNK 4096
#define NCHUNK2 ((2 * NHIST) / CHUNK)  // 2048

// g_cnt layout: [hist round0 | hist round1 | pred hist ALL | pred hist POS]
#define OFF_H0   0
#define OFF_H1   NHIST
#define OFF_HALL (2 * NHIST)
#define OFF_HPOS (3 * NHIST)

__device__ uint32_t g_cnt[4 * NHIST];    // 64MB, one memset
__device__ uint64_t g_recA[NTOT];        // round-0 records (key<<18)|idx
__device__ uint64_t g_recB[NTOT];        // round-1 records
__device__ uint32_t g_k0[NTOT];          // cached threefry keys round 0
__device__ uint32_t g_k1[NTOT];          // cached threefry keys round 1
__device__ uint32_t g_chunkSum[NCHUNK2];
__device__ uint32_t g_chunkBase[NCHUNK2];
__device__ uint8_t  g_t8[NTOT];
__device__ uint8_t  g_lam[NTOT];         // lam[i] = t[r2[i]]
__device__ uint2    g_sub[2][NSAMP];
__device__ unsigned long long g_sum[NSAMP];   // 2 * sum of positive ranks (exact int)
__device__ unsigned int       g_npos[NSAMP];

// ---------------- threefry2x32 (exact JAX semantics) ----------------
__device__ __forceinline__ uint32_t rotl32(uint32_t v, int d) {
    return (v << d) | (v >> (32 - d));
}
__device__ __forceinline__ uint2 threefry2x32(uint32_t k0, uint32_t k1,
                                              uint32_t x0, uint32_t x1) {
    uint32_t ks0 = k0, ks1 = k1, ks2 = k0 ^ k1 ^ 0x1BD11BDAu;
    x0 += ks0; x1 += ks1;
#define TF_RND(r) { x0 += x1; x1 = rotl32(x1, r); x1 ^= x0; }
    TF_RND(13) TF_RND(15) TF_RND(26) TF_RND(6)
    x0 += ks1; x1 += ks2 + 1u;
    TF_RND(17) TF_RND(29) TF_RND(16) TF_RND(24)
    x0 += ks2; x1 += ks0 + 2u;
    TF_RND(13) TF_RND(15) TF_RND(26) TF_RND(6)
    x0 += ks0; x1 += ks1 + 3u;
    TF_RND(17) TF_RND(29) TF_RND(16) TF_RND(24)
    x0 += ks1; x1 += ks2 + 4u;
    TF_RND(13) TF_RND(15) TF_RND(26) TF_RND(6)
    x0 += ks2; x1 += ks0 + 5u;
#undef TF_RND
    return make_uint2(x0, x1);
}

// init: zero accumulators + per-sample subkeys (validated in earlier rounds)
__global__ void init_kernel() {
    int b = threadIdx.x;
    if (b >= NSAMP) return;
    g_sum[b]  = 0ull;
    g_npos[b] = 0u;
    const uint32_t r0 = 0u, r1 = 42u;
    uint2 kb;
    if (b < 32) {
        kb.x = threefry2x32(r0, r1, 2 * b,     64 + 2 * b).x;
        kb.y = threefry2x32(r0, r1, 2 * b + 1, 65 + 2 * b).x;
    } else {
        kb.x = threefry2x32(r0, r1, 2 * b - 64, 2 * b).y;
        kb.y = threefry2x32(r0, r1, 2 * b - 63, 2 * b + 1).y;
    }
    uint2 t0 = threefry2x32(kb.x, kb.y, 0u, 2u);
    uint2 t1 = threefry2x32(kb.x, kb.y, 1u, 3u);
    uint2 newk = make_uint2(t0.x, t1.x);
    g_sub[0][b] = make_uint2(t0.y, t1.y);          // round-1 (first shuffle sort)
    uint2 s0 = threefry2x32(newk.x, newk.y, 0u, 2u);
    uint2 s1 = threefry2x32(newk.x, newk.y, 1u, 3u);
    g_sub[1][b] = make_uint2(s0.y, s1.y);          // round-2 (second shuffle sort)
}

__device__ __forceinline__ uint32_t f2sortable(float f) {
    uint32_t u = __float_as_uint(f);
    return (u & 0x80000000u) ? ~u : (u | 0x80000000u);
}

// labels -> bytes + npos + pred-code histogram (ALL). 8 elements/thread.
__global__ void t8_hist_kernel(const int* __restrict__ truem,
                               const float* __restrict__ pred) {
    int base = (blockIdx.x * blockDim.x + threadIdx.x) * 8;
    int b = base >> 18;
    int4 v0 = *reinterpret_cast<const int4*>(truem + base);
    int4 v1 = *reinterpret_cast<const int4*>(truem + base + 4);
    uchar4 c0, c1;
    c0.x = v0.x > 0; c0.y = v0.y > 0; c0.z = v0.z > 0; c0.w = v0.w > 0;
    c1.x = v1.x > 0; c1.y = v1.y > 0; c1.z = v1.z > 0; c1.w = v1.w > 0;
    *reinterpret_cast<uchar4*>(g_t8 + base)     = c0;
    *reinterpret_cast<uchar4*>(g_t8 + base + 4) = c1;

    float4 p0 = *reinterpret_cast<const float4*>(pred + base);
    float4 p1 = *reinterpret_cast<const float4*>(pred + base + 4);
    uint32_t* h = g_cnt + OFF_HALL + (b << 16);
    atomicAdd(&h[f2sortable(p0.x) >> 16], 1u);
    atomicAdd(&h[f2sortable(p0.y) >> 16], 1u);
    atomicAdd(&h[f2sortable(p0.z) >> 16], 1u);
    atomicAdd(&h[f2sortable(p0.w) >> 16], 1u);
    atomicAdd(&h[f2sortable(p1.x) >> 16], 1u);
    atomicAdd(&h[f2sortable(p1.y) >> 16], 1u);
    atomicAdd(&h[f2sortable(p1.z) >> 16], 1u);
    atomicAdd(&h[f2sortable(p1.w) >> 16], 1u);

    unsigned cnt = (unsigned)(c0.x + c0.y + c0.z + c0.w + c1.x + c1.y + c1.z + c1.w);
    for (int o = 16; o > 0; o >>= 1) cnt += __shfl_down_sync(0xFFFFFFFFu, cnt, o);
    __shared__ unsigned sc[8];
    int lane = threadIdx.x & 31, w = threadIdx.x >> 5;
    if (lane == 0) sc[w] = cnt;
    __syncthreads();
    if (threadIdx.x == 0) {
        unsigned s = 0;
        #pragma unroll
        for (int k = 0; k < 8; k++) s += sc[k];
        atomicAdd(&g_npos[b], s);
    }
}

// Compute threefry keys for BOTH rounds, cache them, histogram top-16 bits.
__global__ void keys_hist_kernel() {
    int i = blockIdx.x * blockDim.x + threadIdx.x;  // [0, NSAMP*HPER)
    int b = i >> 17, loc = i & (HPER - 1);
    int g0 = (b << 18) + loc;
    #pragma unroll
    for (int r = 0; r < 2; r++) {
        uint2 s = g_sub[r][b];
        uint2 y = threefry2x32(s.x, s.y, (uint32_t)loc, (uint32_t)(HPER + loc));
        uint32_t* keys = r ? g_k1 : g_k0;
        keys[g0]        = y.x;
        keys[g0 + HPER] = y.y;
        uint32_t* h = g_cnt + (r ? OFF_H1 : OFF_H0) + (b << 16);
        atomicAdd(&h[y.x >> 16], 1u);
        atomicAdd(&h[y.y >> 16], 1u);
    }
}

// chunk-local exclusive scan of g_cnt[0 .. 2*NHIST) in place; chunk totals out.
__global__ void scanA_kernel() {
    typedef cub::BlockScan<uint32_t, 256> BS;
    __shared__ typename BS::TempStorage ts;
    int base = blockIdx.x * CHUNK + threadIdx.x * 16;
    uint4 v[4];
    #pragma unroll
    for (int q = 0; q < 4; q++)
        v[q] = *reinterpret_cast<const uint4*>(g_cnt + base + q * 4);
    uint32_t s = 0;
    #pragma unroll
    for (int q = 0; q < 4; q++) s += v[q].x + v[q].y + v[q].z + v[q].w;
    uint32_t ex, tot;
    BS(ts).ExclusiveSum(s, ex, tot);
    uint32_t run = ex;
    #pragma unroll
    for (int q = 0; q < 4; q++) {
        uint4 o;
        o.x = run; run += v[q].x;
        o.y = run; run += v[q].y;
        o.z = run; run += v[q].z;
        o.w = run; run += v[q].w;
        *reinterpret_cast<uint4*>(g_cnt + base + q * 4) = o;
    }
    if (threadIdx.x == 0) g_chunkSum[blockIdx.x] = tot;
}

// per (round,sample) exclusive scan over its 16 chunk sums
__global__ void scanB_kernel() {
    int t = threadIdx.x + blockIdx.x * blockDim.x;  // 0..2047
    if (t >= NCHUNK2) return;
    int rs = t >> 4, pos = t & 15;
    uint32_t acc = 0;
    for (int j = 0; j < pos; j++) acc += g_chunkSum[(rs << 4) + j];
    g_chunkBase[t] = acc;
}

__device__ __forceinline__ uint32_t chunk_base(int r, int b, uint32_t bucket) {
    return g_chunkBase[((r * NSAMP + b) << 4) | (bucket >> 12)];
}

// scatter (key<<18|idx) records; slot comes from bumping the SCANNED hist,
// so post-scatter hist[bucket] == end of bucket (begin = end of bucket-1).
__global__ void scatter_kernel() {
    int i = blockIdx.x * blockDim.x + threadIdx.x;
    int b = i >> 17, loc = i & (HPER - 1);
    int g0 = (b << 18) + loc;
    #pragma unroll
    for (int r = 0; r < 2; r++) {
        const uint32_t* keys = r ? g_k1 : g_k0;
        uint64_t* rec = r ? g_recB : g_recA;
        uint32_t* hist = g_cnt + (r ? OFF_H1 : OFF_H0) + (b << 16);
        uint32_t k0 = keys[g0], k1 = keys[g0 + HPER];
        {
            uint32_t bucket = k0 >> 16;
            uint32_t slot = atomicAdd(&hist[bucket], 1u) + chunk_base(r, b, bucket);
            rec[(b << 18) + slot] = ((uint64_t)k0 << 18) | (uint32_t)loc;
        }
        {
            uint32_t bucket = k1 >> 16;
            uint32_t slot = atomicAdd(&hist[bucket], 1u) + chunk_base(r, b, bucket);
            rec[(b << 18) + slot] = ((uint64_t)k1 << 18) | (uint32_t)(HPER + loc);
        }
    }
}

// within-bucket stable rank by u64 comparison (rec unique per sample: exact).
// R==1 (round 2): lam[il] = t8[rank].
// R==0 (round 1): if (lam[rank]) histogram pred code of il into HPOS.
template <int R>
__global__ void rank_kernel(const float* __restrict__ pred) {
    int g = blockIdx.x * blockDim.x + threadIdx.x;
    const uint64_t* rec = R ? g_recB : g_recA;
    uint64_t me = rec[g];
    int b = g >> 18, sb = b << 18;
    uint32_t key = (uint32_t)(me >> 18);
    uint32_t bucket = key >> 16;
    const uint32_t* hist = g_cnt + (R ? OFF_H1 : OFF_H0) + (b << 16);
    uint32_t end = hist[bucket] + chunk_base(R, b, bucket);
    uint32_t begin = 0;
    if (bucket) begin = hist[bucket - 1] + chunk_base(R, b, bucket - 1);
    uint32_t r = 0;
    for (uint32_t j = begin; j < end; j++) r += (rec[sb + j] < me) ? 1u : 0u;
    uint32_t rank = begin + r;                       // 0-based stable rank
    uint32_t il = (uint32_t)(me & 0x3FFFFu);
    if (R == 1) {
        g_lam[sb + il] = g_t8[sb + rank];            // near-coalesced gather
    } else if (g_lam[sb + rank]) {
        uint32_t code = f2sortable(pred[sb + il]) >> 16;
        atomicAdd(&g_cnt[OFF_HPOS + (b << 16) + code], 1u);
    }
}

// Closed-form tie-averaged rank sum per sample:
// 2*sum_pos_ranks = sum_bins q*(2B + c + 1), B = running prefix of c.
__global__ void auc_scan_kernel() {
    typedef cub::BlockScan<uint32_t, 256> BS;
    __shared__ typename BS::TempStorage ts;
    int b = blockIdx.x;
    const uint32_t* hall = g_cnt + OFF_HALL + (b << 16);
    const uint32_t* hpos = g_cnt + OFF_HPOS + (b << 16);
    int base = threadIdx.x * 256;                    // 256 bins per thread
    uint32_t tot = 0;
    for (int k = 0; k < 256; k += 4) {
        uint4 c = *reinterpret_cast<const uint4*>(hall + base + k);
        tot += c.x + c.y + c.z + c.w;
    }
    uint32_t B0;
    BS(ts).ExclusiveSum(tot, B0);
    unsigned long long acc = 0ull;
    uint32_t B = B0;
    for (int k = 0; k < 256; k += 4) {
        uint4 c = *reinterpret_cast<const uint4*>(hall + base + k);
        uint4 q = *reinterpret_cast<const uint4*>(hpos + base + k);
        acc += (unsigned long long)q.x * (2u * B + c.x + 1u); B += c.x;
        acc += (unsigned long long)q.y * (2u * B + c.y + 1u); B += c.y;
        acc += (unsigned long long)q.z * (2u * B + c.z + 1u); B += c.z;
        acc += (unsigned long long)q.w * (2u * B + c.w + 1u); B += c.w;
    }
    for (int o = 16; o > 0; o >>= 1) acc += __shfl_down_sync(0xFFFFFFFFu, acc, o);
    __shared__ unsigned long long sacc[8];
    int lane = threadIdx.x & 31, w = threadIdx.x >> 5;
    if (lane == 0) sacc[w] = acc;
    __syncthreads();
    if (threadIdx.x == 0) {
        unsigned long long s = 0ull;
        #pragma unroll
        for (int k = 0; k < 8; k++) s += sacc[k];
        g_sum[b] = s;                                // deterministic plain store
    }
}

__global__ void finalize_kernel(float* __restrict__ out) {
    __shared__ double aucs[NSAMP];
    int b = threadIdx.x;
    if (b < NSAMP) {
        double np = (double)g_npos[b];
        double nn = (double)NPER - np;
        double spr = 0.5 * (double)g_sum[b];         // g_sum holds 2*sum_pos_ranks
        aucs[b] = (spr - np * (np + 1.0) * 0.5) / (np * nn);
    }
    __syncthreads();
    if (b == 0) {
        double tot = 0.0;
        for (int k = 0; k < NSAMP; k++) tot += aucs[k];
        out[0] = (float)(tot / (double)NSAMP);
    }
}

extern "C" void kernel_launch(void* const* d_in, const int* in_sizes, int n_in,
                              void* d_out, int out_size) {
    const float* pred  = (const float*)d_in[0];
    const int*   truem = (const int*)d_in[1];
    float*       out   = (float*)d_out;
    cudaStream_t st = 0;

    uint32_t* cnt;
    cudaGetSymbolAddress((void**)&cnt, g_cnt);

    const int TPB = 256;
    const int GRID_ALL  = NTOT / TPB;                 // 65536
    const int GRID_HALF = (NSAMP * HPER) / TPB;       // 32768
    const int GRID_8    = NTOT / (TPB * 8);           // 8192

    init_kernel<<<1, 64, 0, st>>>();
    cudaMemsetAsync(cnt, 0, 4ull * NHIST * 4, st);    // 64MB: both round hists + HALL + HPOS
    t8_hist_kernel<<<GRID_8, TPB, 0, st>>>(truem, pred);

    // ---- both shuffle rounds: keys+hist, scan, scatter, ranks ----
    keys_hist_kernel<<<GRID_HALF, TPB, 0, st>>>();
    scanA_kernel<<<NCHUNK2, 256, 0, st>>>();
    scanB_kernel<<<NCHUNK2 / 256, 256, 0, st>>>();
    scatter_kernel<<<GRID_HALF, TPB, 0, st>>>();
    rank_kernel<1><<<GRID_ALL, TPB, 0, st>>>(pred);   // lam[i] = t8[r2[i]]
    rank_kernel<0><<<GRID_ALL, TPB, 0, st>>>(pred);   // HPOS[code(pred[k])] += lam[r1[k]]

    // ---- closed-form AUC from histograms ----
    auc_scan_kernel<<<NSAMP, 256, 0, st>>>();
    finalize_kernel<<<1, 64, 0, st>>>(out);
}

// round 8
// speedup vs baseline: 1.5940x; 1.5940x over previous
#include <cuda_runtime.h>
#include <cuda_bf16.h>
#include <cub/cub.cuh>
#include <cstdint>

// AUCShuffled: B=64 samples x N=2^18 preds.
// answer_b = sum_k rankavg0[k] * m[k],  m[k] = lam[r1[k]],  lam[i] = t[r2[i]]
//  - r1,r2 = stable ranks of uniform threefry keys via bucket counting sort
//  - rankavg0 sum via closed form over a 13-bit pred histogram:
//      2*sum = sum_bins q*(2B + c + 1)
// R8: smem-privatized pred histograms (HALL in t8_hist, HPOS in rank0) to kill
//     L2 atomic contention from the normal-distributed pred codes.

#define NSAMP 64
#define NPER  262144            // 2^18
#define HPER  131072            // 2^17
#define NTOT  (NSAMP * NPER)    // 16,777,216
#define NBUCK 65536             // key buckets per sample (top 16 bits)
#define NHIST (NSAMP * NBUCK)   // 4,194,304 per round
#define CHUNK 4096
#define NCHUNK2 ((2 * NHIST) / CHUNK)  // 2048

#define PBITS 13
#define PBIN  8192              // pred bins per sample (32KB smem hist)
#define PSH   (32 - PBITS)      // shift for pred code

// g_cnt layout: [hist round0 | hist round1 | pred hist ALL | pred hist POS]
#define OFF_H0   0
#define OFF_H1   NHIST
#define OFF_HALL (2 * NHIST)
#define OFF_HPOS (2 * NHIST + NSAMP * PBIN)
#define CNT_TOTAL (2 * NHIST + 2 * NSAMP * PBIN)   // 9,437,184 u32 = 37.7MB

__device__ uint32_t g_cnt[CNT_TOTAL];
__device__ uint64_t g_recA[NTOT];        // round-0 records (key<<18)|idx
__device__ uint64_t g_recB[NTOT];        // round-1 records
__device__ uint32_t g_k0[NTOT];          // cached threefry keys round 0
__device__ uint32_t g_k1[NTOT];          // cached threefry keys round 1
__device__ uint32_t g_chunkSum[NCHUNK2];
__device__ uint32_t g_chunkBase[NCHUNK2];
__device__ uint8_t  g_t8[NTOT];
__device__ uint8_t  g_lam[NTOT];         // lam[i] = t[r2[i]]
__device__ uint2    g_sub[2][NSAMP];
__device__ unsigned long long g_sum[NSAMP];   // 2 * sum of positive ranks
__device__ unsigned int       g_npos[NSAMP];

// ---------------- threefry2x32 (exact JAX semantics) ----------------
__device__ __forceinline__ uint32_t rotl32(uint32_t v, int d) {
    return (v << d) | (v >> (32 - d));
}
__device__ __forceinline__ uint2 threefry2x32(uint32_t k0, uint32_t k1,
                                              uint32_t x0, uint32_t x1) {
    uint32_t ks0 = k0, ks1 = k1, ks2 = k0 ^ k1 ^ 0x1BD11BDAu;
    x0 += ks0; x1 += ks1;
#define TF_RND(r) { x0 += x1; x1 = rotl32(x1, r); x1 ^= x0; }
    TF_RND(13) TF_RND(15) TF_RND(26) TF_RND(6)
    x0 += ks1; x1 += ks2 + 1u;
    TF_RND(17) TF_RND(29) TF_RND(16) TF_RND(24)
    x0 += ks2; x1 += ks0 + 2u;
    TF_RND(13) TF_RND(15) TF_RND(26) TF_RND(6)
    x0 += ks0; x1 += ks1 + 3u;
    TF_RND(17) TF_RND(29) TF_RND(16) TF_RND(24)
    x0 += ks1; x1 += ks2 + 4u;
    TF_RND(13) TF_RND(15) TF_RND(26) TF_RND(6)
    x0 += ks2; x1 += ks0 + 5u;
#undef TF_RND
    return make_uint2(x0, x1);
}

__global__ void init_kernel() {
    int b = threadIdx.x;
    if (b >= NSAMP) return;
    g_sum[b]  = 0ull;
    g_npos[b] = 0u;
    const uint32_t r0 = 0u, r1 = 42u;
    uint2 kb;
    if (b < 32) {
        kb.x = threefry2x32(r0, r1, 2 * b,     64 + 2 * b).x;
        kb.y = threefry2x32(r0, r1, 2 * b + 1, 65 + 2 * b).x;
    } else {
        kb.x = threefry2x32(r0, r1, 2 * b - 64, 2 * b).y;
        kb.y = threefry2x32(r0, r1, 2 * b - 63, 2 * b + 1).y;
    }
    uint2 t0 = threefry2x32(kb.x, kb.y, 0u, 2u);
    uint2 t1 = threefry2x32(kb.x, kb.y, 1u, 3u);
    uint2 newk = make_uint2(t0.x, t1.x);
    g_sub[0][b] = make_uint2(t0.y, t1.y);          // round-1 (first shuffle sort)
    uint2 s0 = threefry2x32(newk.x, newk.y, 0u, 2u);
    uint2 s1 = threefry2x32(newk.x, newk.y, 1u, 3u);
    g_sub[1][b] = make_uint2(s0.y, s1.y);          // round-2 (second shuffle sort)
}

__device__ __forceinline__ uint32_t f2sortable(float f) {
    uint32_t u = __float_as_uint(f);
    return (u & 0x80000000u) ? ~u : (u | 0x80000000u);
}

// labels -> bytes + npos + smem-privatized pred histogram (HALL).
// 1024 threads x 32 elements = 32768 el/block, 8 blocks per sample.
__global__ __launch_bounds__(1024) void t8_hist_kernel(
        const int* __restrict__ truem, const float* __restrict__ pred) {
    __shared__ uint32_t sh[PBIN];                  // 32KB
    for (int j = threadIdx.x; j < PBIN; j += 1024) sh[j] = 0;
    __syncthreads();
    int blockBase = blockIdx.x * 32768;
    int b = blockBase >> 18;
    unsigned cnt = 0;
    #pragma unroll
    for (int e = 0; e < 8; e++) {
        int base = blockBase + e * 4096 + threadIdx.x * 4;
        int4  v = *reinterpret_cast<const int4*>(truem + base);
        float4 p = *reinterpret_cast<const float4*>(pred + base);
        uchar4 c;
        c.x = v.x > 0; c.y = v.y > 0; c.z = v.z > 0; c.w = v.w > 0;
        *reinterpret_cast<uchar4*>(g_t8 + base) = c;
        cnt += (unsigned)(c.x + c.y + c.z + c.w);
        atomicAdd(&sh[f2sortable(p.x) >> PSH], 1u);
        atomicAdd(&sh[f2sortable(p.y) >> PSH], 1u);
        atomicAdd(&sh[f2sortable(p.z) >> PSH], 1u);
        atomicAdd(&sh[f2sortable(p.w) >> PSH], 1u);
    }
    for (int o = 16; o > 0; o >>= 1) cnt += __shfl_down_sync(0xFFFFFFFFu, cnt, o);
    __shared__ unsigned sc[32];
    int lane = threadIdx.x & 31, w = threadIdx.x >> 5;
    if (lane == 0) sc[w] = cnt;
    __syncthreads();
    if (threadIdx.x == 0) {
        unsigned s = 0;
        #pragma unroll
        for (int k = 0; k < 32; k++) s += sc[k];
        atomicAdd(&g_npos[b], s);
    }
    // flush smem hist (8 blocks share a sample -> atomic, uniform, L2-resident)
    uint32_t* hall = g_cnt + OFF_HALL + (b << PBITS);
    for (int j = threadIdx.x; j < PBIN; j += 1024) {
        uint32_t v = sh[j];
        if (v) atomicAdd(&hall[j], v);
    }
}

// Compute threefry keys for BOTH rounds, cache them, histogram top-16 bits.
// Uniform keys -> negligible atomic contention (L2-resident region).
__global__ void keys_hist_kernel() {
    int i = blockIdx.x * blockDim.x + threadIdx.x;  // [0, NSAMP*HPER)
    int b = i >> 17, loc = i & (HPER - 1);
    int g0 = (b << 18) + loc;
    #pragma unroll
    for (int r = 0; r < 2; r++) {
        uint2 s = g_sub[r][b];
        uint2 y = threefry2x32(s.x, s.y, (uint32_t)loc, (uint32_t)(HPER + loc));
        uint32_t* keys = r ? g_k1 : g_k0;
        keys[g0]        = y.x;
        keys[g0 + HPER] = y.y;
        uint32_t* h = g_cnt + (r ? OFF_H1 : OFF_H0) + (b << 16);
        atomicAdd(&h[y.x >> 16], 1u);
        atomicAdd(&h[y.y >> 16], 1u);
    }
}

// chunk-local exclusive scan of g_cnt[0 .. 2*NHIST) in place; chunk totals out.
__global__ void scanA_kernel() {
    typedef cub::BlockScan<uint32_t, 256> BS;
    __shared__ typename BS::TempStorage ts;
    int base = blockIdx.x * CHUNK + threadIdx.x * 16;
    uint4 v[4];
    #pragma unroll
    for (int q = 0; q < 4; q++)
        v[q] = *reinterpret_cast<const uint4*>(g_cnt + base + q * 4);
    uint32_t s = 0;
    #pragma unroll
    for (int q = 0; q < 4; q++) s += v[q].x + v[q].y + v[q].z + v[q].w;
    uint32_t ex, tot;
    BS(ts).ExclusiveSum(s, ex, tot);
    uint32_t run = ex;
    #pragma unroll
    for (int q = 0; q < 4; q++) {
        uint4 o;
        o.x = run; run += v[q].x;
        o.y = run; run += v[q].y;
        o.z = run; run += v[q].z;
        o.w = run; run += v[q].w;
        *reinterpret_cast<uint4*>(g_cnt + base + q * 4) = o;
    }
    if (threadIdx.x == 0) g_chunkSum[blockIdx.x] = tot;
}

// per (round,sample) exclusive scan over its 16 chunk sums
__global__ void scanB_kernel() {
    int t = threadIdx.x + blockIdx.x * blockDim.x;
    if (t >= NCHUNK2) return;
    int rs = t >> 4, pos = t & 15;
    uint32_t acc = 0;
    for (int j = 0; j < pos; j++) acc += g_chunkSum[(rs << 4) + j];
    g_chunkBase[t] = acc;
}

__device__ __forceinline__ uint32_t chunk_base(int r, int b, uint32_t bucket) {
    return g_chunkBase[((r * NSAMP + b) << 4) | (bucket >> 12)];
}

// scatter (key<<18|idx) records; slot from bumping the SCANNED hist, so
// post-scatter hist[bucket] == end of bucket (begin = end of bucket-1).
__global__ void scatter_kernel() {
    int i = blockIdx.x * blockDim.x + threadIdx.x;
    int b = i >> 17, loc = i & (HPER - 1);
    int g0 = (b << 18) + loc;
    #pragma unroll
    for (int r = 0; r < 2; r++) {
        const uint32_t* keys = r ? g_k1 : g_k0;
        uint64_t* rec = r ? g_recB : g_recA;
        uint32_t* hist = g_cnt + (r ? OFF_H1 : OFF_H0) + (b << 16);
        uint32_t k0 = keys[g0], k1 = keys[g0 + HPER];
        {
            uint32_t bucket = k0 >> 16;
            uint32_t slot = atomicAdd(&hist[bucket], 1u) + chunk_base(r, b, bucket);
            rec[(b << 18) + slot] = ((uint64_t)k0 << 18) | (uint32_t)loc;
        }
        {
            uint32_t bucket = k1 >> 16;
            uint32_t slot = atomicAdd(&hist[bucket], 1u) + chunk_base(r, b, bucket);
            rec[(b << 18) + slot] = ((uint64_t)k1 << 18) | (uint32_t)(HPER + loc);
        }
    }
}

// round 2: within-bucket stable rank -> lam[il] = t8[rank]
__global__ void rank1_kernel() {
    int g = blockIdx.x * blockDim.x + threadIdx.x;
    uint64_t me = g_recB[g];
    int b = g >> 18, sb = b << 18;
    uint32_t bucket = (uint32_t)(me >> 34);          // top 16 key bits
    const uint32_t* hist = g_cnt + OFF_H1 + (b << 16);
    uint32_t end = hist[bucket] + chunk_base(1, b, bucket);
    uint32_t begin = 0;
    if (bucket) begin = hist[bucket - 1] + chunk_base(1, b, bucket - 1);
    uint32_t r = 0;
    for (uint32_t j = begin; j < end; j++) r += (g_recB[sb + j] < me) ? 1u : 0u;
    uint32_t rank = begin + r;
    uint32_t il = (uint32_t)(me & 0x3FFFFu);
    g_lam[sb + il] = g_t8[sb + rank];                // write to 16MB L2-resident
}

// round 1: rank -> m = lam[rank]; if positive, smem-privatized HPOS histogram.
// 1024 threads x 16 elements = 16384 el/block, 16 blocks per sample.
__global__ __launch_bounds__(1024) void rank0_kernel(const float* __restrict__ pred) {
    __shared__ uint32_t sh[PBIN];                    // 32KB
    for (int j = threadIdx.x; j < PBIN; j += 1024) sh[j] = 0;
    __syncthreads();
    int blockBase = blockIdx.x * 16384;
    int b = blockBase >> 18, sb = b << 18;
    const uint32_t* hist = g_cnt + OFF_H0 + (b << 16);
    #pragma unroll
    for (int e = 0; e < 16; e++) {
        int g = blockBase + e * 1024 + threadIdx.x;
        uint64_t me = g_recA[g];
        uint32_t bucket = (uint32_t)(me >> 34);
        uint32_t end = hist[bucket] + chunk_base(0, b, bucket);
        uint32_t begin = 0;
        if (bucket) begin = hist[bucket - 1] + chunk_base(0, b, bucket - 1);
        uint32_t r = 0;
        for (uint32_t j = begin; j < end; j++) r += (g_recA[sb + j] < me) ? 1u : 0u;
        uint32_t rank = begin + r;
        if (g_lam[sb + rank]) {
            uint32_t il = (uint32_t)(me & 0x3FFFFu);
            uint32_t code = f2sortable(pred[sb + il]) >> PSH;
            atomicAdd(&sh[code], 1u);
        }
    }
    __syncthreads();
    uint32_t* hpos = g_cnt + OFF_HPOS + (b << PBITS);
    for (int j = threadIdx.x; j < PBIN; j += 1024) {
        uint32_t v = sh[j];
        if (v) atomicAdd(&hpos[j], v);
    }
}

// Closed-form tie-averaged rank sum per sample:
// 2*sum_pos_ranks = sum_bins q*(2B + c + 1), B = running prefix of c.
__global__ void auc_scan_kernel() {
    typedef cub::BlockScan<uint32_t, 256> BS;
    __shared__ typename BS::TempStorage ts;
    int b = blockIdx.x;
    const uint32_t* hall = g_cnt + OFF_HALL + (b << PBITS);
    const uint32_t* hpos = g_cnt + OFF_HPOS + (b << PBITS);
    int base = threadIdx.x * (PBIN / 256);           // 32 bins per thread
    uint32_t tot = 0;
    for (int k = 0; k < PBIN / 256; k += 4) {
        uint4 c = *reinterpret_cast<const uint4*>(hall + base + k);
        tot += c.x + c.y + c.z + c.w;
    }
    uint32_t B0;
    BS(ts).ExclusiveSum(tot, B0);
    unsigned long long acc = 0ull;
    uint32_t B = B0;
    for (int k = 0; k < PBIN / 256; k += 4) {
        uint4 c = *reinterpret_cast<const uint4*>(hall + base + k);
        uint4 q = *reinterpret_cast<const uint4*>(hpos + base + k);
        acc += (unsigned long long)q.x * (2u * B + c.x + 1u); B += c.x;
        acc += (unsigned long long)q.y * (2u * B + c.y + 1u); B += c.y;
        acc += (unsigned long long)q.z * (2u * B + c.z + 1u); B += c.z;
        acc += (unsigned long long)q.w * (2u * B + c.w + 1u); B += c.w;
    }
    for (int o = 16; o > 0; o >>= 1) acc += __shfl_down_sync(0xFFFFFFFFu, acc, o);
    __shared__ unsigned long long sacc[8];
    int lane = threadIdx.x & 31, w = threadIdx.x >> 5;
    if (lane == 0) sacc[w] = acc;
    __syncthreads();
    if (threadIdx.x == 0) {
        unsigned long long s = 0ull;
        #pragma unroll
        for (int k = 0; k < 8; k++) s += sacc[k];
        g_sum[b] = s;                                // deterministic plain store
    }
}

__global__ void finalize_kernel(float* __restrict__ out) {
    __shared__ double aucs[NSAMP];
    int b = threadIdx.x;
    if (b < NSAMP) {
        double np = (double)g_npos[b];
        double nn = (double)NPER - np;
        double spr = 0.5 * (double)g_sum[b];
        aucs[b] = (spr - np * (np + 1.0) * 0.5) / (np * nn);
    }
    __syncthreads();
    if (b == 0) {
        double tot = 0.0;
        for (int k = 0; k < NSAMP; k++) tot += aucs[k];
        out[0] = (float)(tot / (double)NSAMP);
    }
}

extern "C" void kernel_launch(void* const* d_in, const int* in_sizes, int n_in,
                              void* d_out, int out_size) {
    const float* pred  = (const float*)d_in[0];
    const int*   truem = (const int*)d_in[1];
    float*       out   = (float*)d_out;
    cudaStream_t st = 0;

    uint32_t* cnt;
    cudaGetSymbolAddress((void**)&cnt, g_cnt);

    const int TPB = 256;
    const int GRID_ALL  = NTOT / TPB;                 // 65536
    const int GRID_HALF = (NSAMP * HPER) / TPB;       // 32768

    init_kernel<<<1, 64, 0, st>>>();
    cudaMemsetAsync(cnt, 0, (size_t)CNT_TOTAL * 4, st);
    t8_hist_kernel<<<NTOT / 32768, 1024, 0, st>>>(truem, pred);

    keys_hist_kernel<<<GRID_HALF, TPB, 0, st>>>();
    scanA_kernel<<<NCHUNK2, 256, 0, st>>>();
    scanB_kernel<<<NCHUNK2 / 256, 256, 0, st>>>();
    scatter_kernel<<<GRID_HALF, TPB, 0, st>>>();
    rank1_kernel<<<GRID_ALL, TPB, 0, st>>>();         // lam[i] = t8[r2[i]]
    rank0_kernel<<<NTOT / 16384, 1024, 0, st>>>(pred);// HPOS[code(pred[k])] += lam[r1[k]]

    auc_scan_kernel<<<NSAMP, 256, 0, st>>>();
    finalize_kernel<<<1, 64, 0, st>>>(out);
}

// round 9
// speedup vs baseline: 1.6267x; 1.0205x over previous
#include <cuda_runtime.h>
#include <cuda_bf16.h>
#include <cub/cub.cuh>
#include <cstdint>

// AUCShuffled: B=64 samples x N=2^18 preds.
// answer_b = sum_k rankavg0[k] * m[k],  m[k] = lam[r1[k]],  lam[i] = t[r2[i]]
//  - r1,r2 = stable ranks of uniform threefry keys via bucket counting sort
//  - rankavg0 sum via closed form over a 13-bit pred histogram:
//      2*sum = sum_bins q*(2B + c + 1)
// R9: key caches removed (threefry regenerated in scatter); per-round
//     scatter->rank sequencing so rank's record reads hit L2 while hot.

#define NSAMP 64
#define NPER  262144            // 2^18
#define HPER  131072            // 2^17
#define NTOT  (NSAMP * NPER)    // 16,777,216
#define NBUCK 65536             // key buckets per sample (top 16 bits)
#define NHIST (NSAMP * NBUCK)   // 4,194,304 per round
#define CHUNK 4096
#define NCHUNK2 ((2 * NHIST) / CHUNK)  // 2048

#define PBITS 13
#define PBIN  8192              // pred bins per sample (32KB smem hist)
#define PSH   (32 - PBITS)

// g_cnt layout: [hist round0 | hist round1 | pred hist ALL | pred hist POS]
#define OFF_H0   0
#define OFF_H1   NHIST
#define OFF_HALL (2 * NHIST)
#define OFF_HPOS (2 * NHIST + NSAMP * PBIN)
#define CNT_TOTAL (2 * NHIST + 2 * NSAMP * PBIN)

__device__ uint32_t g_cnt[CNT_TOTAL];
__device__ uint64_t g_recA[NTOT];        // round-0 records (key<<18)|idx
__device__ uint64_t g_recB[NTOT];        // round-1 records
__device__ uint32_t g_chunkSum[NCHUNK2];
__device__ uint32_t g_chunkBase[NCHUNK2];
__device__ uint8_t  g_t8[NTOT];
__device__ uint8_t  g_lam[NTOT];         // lam[i] = t[r2[i]]
__device__ uint2    g_sub[2][NSAMP];
__device__ unsigned long long g_sum[NSAMP];   // 2 * sum of positive ranks
__device__ unsigned int       g_npos[NSAMP];

// ---------------- threefry2x32 (exact JAX semantics) ----------------
__device__ __forceinline__ uint32_t rotl32(uint32_t v, int d) {
    return (v << d) | (v >> (32 - d));
}
__device__ __forceinline__ uint2 threefry2x32(uint32_t k0, uint32_t k1,
                                              uint32_t x0, uint32_t x1) {
    uint32_t ks0 = k0, ks1 = k1, ks2 = k0 ^ k1 ^ 0x1BD11BDAu;
    x0 += ks0; x1 += ks1;
#define TF_RND(r) { x0 += x1; x1 = rotl32(x1, r); x1 ^= x0; }
    TF_RND(13) TF_RND(15) TF_RND(26) TF_RND(6)
    x0 += ks1; x1 += ks2 + 1u;
    TF_RND(17) TF_RND(29) TF_RND(16) TF_RND(24)
    x0 += ks2; x1 += ks0 + 2u;
    TF_RND(13) TF_RND(15) TF_RND(26) TF_RND(6)
    x0 += ks0; x1 += ks1 + 3u;
    TF_RND(17) TF_RND(29) TF_RND(16) TF_RND(24)
    x0 += ks1; x1 += ks2 + 4u;
    TF_RND(13) TF_RND(15) TF_RND(26) TF_RND(6)
    x0 += ks2; x1 += ks0 + 5u;
#undef TF_RND
    return make_uint2(x0, x1);
}

__global__ void init_kernel() {
    int b = threadIdx.x;
    if (b >= NSAMP) return;
    g_sum[b]  = 0ull;
    g_npos[b] = 0u;
    const uint32_t r0 = 0u, r1 = 42u;
    uint2 kb;
    if (b < 32) {
        kb.x = threefry2x32(r0, r1, 2 * b,     64 + 2 * b).x;
        kb.y = threefry2x32(r0, r1, 2 * b + 1, 65 + 2 * b).x;
    } else {
        kb.x = threefry2x32(r0, r1, 2 * b - 64, 2 * b).y;
        kb.y = threefry2x32(r0, r1, 2 * b - 63, 2 * b + 1).y;
    }
    uint2 t0 = threefry2x32(kb.x, kb.y, 0u, 2u);
    uint2 t1 = threefry2x32(kb.x, kb.y, 1u, 3u);
    uint2 newk = make_uint2(t0.x, t1.x);
    g_sub[0][b] = make_uint2(t0.y, t1.y);          // round-1 (first shuffle sort)
    uint2 s0 = threefry2x32(newk.x, newk.y, 0u, 2u);
    uint2 s1 = threefry2x32(newk.x, newk.y, 1u, 3u);
    g_sub[1][b] = make_uint2(s0.y, s1.y);          // round-2 (second shuffle sort)
}

__device__ __forceinline__ uint32_t f2sortable(float f) {
    uint32_t u = __float_as_uint(f);
    return (u & 0x80000000u) ? ~u : (u | 0x80000000u);
}

// labels -> bytes + npos + smem-privatized pred histogram (HALL).
__global__ __launch_bounds__(1024) void t8_hist_kernel(
        const int* __restrict__ truem, const float* __restrict__ pred) {
    __shared__ uint32_t sh[PBIN];                  // 32KB
    for (int j = threadIdx.x; j < PBIN; j += 1024) sh[j] = 0;
    __syncthreads();
    int blockBase = blockIdx.x * 32768;
    int b = blockBase >> 18;
    unsigned cnt = 0;
    #pragma unroll
    for (int e = 0; e < 8; e++) {
        int base = blockBase + e * 4096 + threadIdx.x * 4;
        int4  v = *reinterpret_cast<const int4*>(truem + base);
        float4 p = *reinterpret_cast<const float4*>(pred + base);
        uchar4 c;
        c.x = v.x > 0; c.y = v.y > 0; c.z = v.z > 0; c.w = v.w > 0;
        *reinterpret_cast<uchar4*>(g_t8 + base) = c;
        cnt += (unsigned)(c.x + c.y + c.z + c.w);
        atomicAdd(&sh[f2sortable(p.x) >> PSH], 1u);
        atomicAdd(&sh[f2sortable(p.y) >> PSH], 1u);
        atomicAdd(&sh[f2sortable(p.z) >> PSH], 1u);
        atomicAdd(&sh[f2sortable(p.w) >> PSH], 1u);
    }
    for (int o = 16; o > 0; o >>= 1) cnt += __shfl_down_sync(0xFFFFFFFFu, cnt, o);
    __shared__ unsigned sc[32];
    int lane = threadIdx.x & 31, w = threadIdx.x >> 5;
    if (lane == 0) sc[w] = cnt;
    __syncthreads();
    if (threadIdx.x == 0) {
        unsigned s = 0;
        #pragma unroll
        for (int k = 0; k < 32; k++) s += sc[k];
        atomicAdd(&g_npos[b], s);
    }
    uint32_t* hall = g_cnt + OFF_HALL + (b << PBITS);
    for (int j = threadIdx.x; j < PBIN; j += 1024) {
        uint32_t v = sh[j];
        if (v) atomicAdd(&hall[j], v);
    }
}

// histogram top-16 key bits for both rounds; keys NOT stored (regenerated later)
__global__ void keys_hist_kernel() {
    int i = blockIdx.x * blockDim.x + threadIdx.x;  // [0, NSAMP*HPER)
    int b = i >> 17, loc = i & (HPER - 1);
    #pragma unroll
    for (int r = 0; r < 2; r++) {
        uint2 s = g_sub[r][b];
        uint2 y = threefry2x32(s.x, s.y, (uint32_t)loc, (uint32_t)(HPER + loc));
        uint32_t* h = g_cnt + (r ? OFF_H1 : OFF_H0) + (b << 16);
        atomicAdd(&h[y.x >> 16], 1u);
        atomicAdd(&h[y.y >> 16], 1u);
    }
}

// chunk-local exclusive scan of g_cnt[0 .. 2*NHIST) in place; chunk totals out.
__global__ void scanA_kernel() {
    typedef cub::BlockScan<uint32_t, 256> BS;
    __shared__ typename BS::TempStorage ts;
    int base = blockIdx.x * CHUNK + threadIdx.x * 16;
    uint4 v[4];
    #pragma unroll
    for (int q = 0; q < 4; q++)
        v[q] = *reinterpret_cast<const uint4*>(g_cnt + base + q * 4);
    uint32_t s = 0;
    #pragma unroll
    for (int q = 0; q < 4; q++) s += v[q].x + v[q].y + v[q].z + v[q].w;
    uint32_t ex, tot;
    BS(ts).ExclusiveSum(s, ex, tot);
    uint32_t run = ex;
    #pragma unroll
    for (int q = 0; q < 4; q++) {
        uint4 o;
        o.x = run; run += v[q].x;
        o.y = run; run += v[q].y;
        o.z = run; run += v[q].z;
        o.w = run; run += v[q].w;
        *reinterpret_cast<uint4*>(g_cnt + base + q * 4) = o;
    }
    if (threadIdx.x == 0) g_chunkSum[blockIdx.x] = tot;
}

// per (round,sample) exclusive scan over its 16 chunk sums
__global__ void scanB_kernel() {
    int t = threadIdx.x + blockIdx.x * blockDim.x;
    if (t >= NCHUNK2) return;
    int rs = t >> 4, pos = t & 15;
    uint32_t acc = 0;
    for (int j = 0; j < pos; j++) acc += g_chunkSum[(rs << 4) + j];
    g_chunkBase[t] = acc;
}

__device__ __forceinline__ uint32_t chunk_base(int r, int b, uint32_t bucket) {
    return g_chunkBase[((r * NSAMP + b) << 4) | (bucket >> 12)];
}

// scatter one round: regenerate keys, slot from bumping the SCANNED hist
// (post-scatter hist[bucket] == end of bucket; begin = end of bucket-1).
template <int R>
__global__ void scatter_kernel() {
    int i = blockIdx.x * blockDim.x + threadIdx.x;
    int b = i >> 17, loc = i & (HPER - 1);
    uint2 s = g_sub[R][b];
    uint2 y = threefry2x32(s.x, s.y, (uint32_t)loc, (uint32_t)(HPER + loc));
    uint64_t* rec = R ? g_recB : g_recA;
    uint32_t* hist = g_cnt + (R ? OFF_H1 : OFF_H0) + (b << 16);
    {
        uint32_t bucket = y.x >> 16;
        uint32_t slot = atomicAdd(&hist[bucket], 1u) + chunk_base(R, b, bucket);
        rec[(b << 18) + slot] = ((uint64_t)y.x << 18) | (uint32_t)loc;
    }
    {
        uint32_t bucket = y.y >> 16;
        uint32_t slot = atomicAdd(&hist[bucket], 1u) + chunk_base(R, b, bucket);
        rec[(b << 18) + slot] = ((uint64_t)y.y << 18) | (uint32_t)(HPER + loc);
    }
}

// round 2: within-bucket stable rank -> lam[il] = t8[rank]
__global__ void rank1_kernel() {
    int g = blockIdx.x * blockDim.x + threadIdx.x;
    uint64_t me = g_recB[g];
    int b = g >> 18, sb = b << 18;
    uint32_t bucket = (uint32_t)(me >> 34);          // top 16 key bits
    const uint32_t* hist = g_cnt + OFF_H1 + (b << 16);
    uint32_t end = hist[bucket] + chunk_base(1, b, bucket);
    uint32_t begin = 0;
    if (bucket) begin = hist[bucket - 1] + chunk_base(1, b, bucket - 1);
    uint32_t r = 0;
    for (uint32_t j = begin; j < end; j++) r += (g_recB[sb + j] < me) ? 1u : 0u;
    uint32_t rank = begin + r;
    uint32_t il = (uint32_t)(me & 0x3FFFFu);
    g_lam[sb + il] = g_t8[sb + rank];
}

// round 1: rank -> m = lam[rank]; if positive, smem-privatized HPOS histogram.
__global__ __launch_bounds__(1024) void rank0_kernel(const float* __restrict__ pred) {
    __shared__ uint32_t sh[PBIN];                    // 32KB
    for (int j = threadIdx.x; j < PBIN; j += 1024) sh[j] = 0;
    __syncthreads();
    int blockBase = blockIdx.x * 16384;
    int b = blockBase >> 18, sb = b << 18;
    const uint32_t* hist = g_cnt + OFF_H0 + (b << 16);
    #pragma unroll
    for (int e = 0; e < 16; e++) {
        int g = blockBase + e * 1024 + threadIdx.x;
        uint64_t me = g_recA[g];
        uint32_t bucket = (uint32_t)(me >> 34);
        uint32_t end = hist[bucket] + chunk_base(0, b, bucket);
        uint32_t begin = 0;
        if (bucket) begin = hist[bucket - 1] + chunk_base(0, b, bucket - 1);
        uint32_t r = 0;
        for (uint32_t j = begin; j < end; j++) r += (g_recA[sb + j] < me) ? 1u : 0u;
        uint32_t rank = begin + r;
        if (g_lam[sb + rank]) {
            uint32_t il = (uint32_t)(me & 0x3FFFFu);
            uint32_t code = f2sortable(pred[sb + il]) >> PSH;
            atomicAdd(&sh[code], 1u);
        }
    }
    __syncthreads();
    uint32_t* hpos = g_cnt + OFF_HPOS + (b << PBITS);
    for (int j = threadIdx.x; j < PBIN; j += 1024) {
        uint32_t v = sh[j];
        if (v) atomicAdd(&hpos[j], v);
    }
}

// Closed-form tie-averaged rank sum per sample:
// 2*sum_pos_ranks = sum_bins q*(2B + c + 1), B = running prefix of c.
__global__ void auc_scan_kernel() {
    typedef cub::BlockScan<uint32_t, 256> BS;
    __shared__ typename BS::TempStorage ts;
    int b = blockIdx.x;
    const uint32_t* hall = g_cnt + OFF_HALL + (b << PBITS);
    const uint32_t* hpos = g_cnt + OFF_HPOS + (b << PBITS);
    int base = threadIdx.x * (PBIN / 256);
    uint32_t tot = 0;
    for (int k = 0; k < PBIN / 256; k += 4) {
        uint4 c = *reinterpret_cast<const uint4*>(hall + base + k);
        tot += c.x + c.y + c.z + c.w;
    }
    uint32_t B0;
    BS(ts).ExclusiveSum(tot, B0);
    unsigned long long acc = 0ull;
    uint32_t B = B0;
    for (int k = 0; k < PBIN / 256; k += 4) {
        uint4 c = *reinterpret_cast<const uint4*>(hall + base + k);
        uint4 q = *reinterpret_cast<const uint4*>(hpos + base + k);
        acc += (unsigned long long)q.x * (2u * B + c.x + 1u); B += c.x;
        acc += (unsigned long long)q.y * (2u * B + c.y + 1u); B += c.y;
        acc += (unsigned long long)q.z * (2u * B + c.z + 1u); B += c.z;
        acc += (unsigned long long)q.w * (2u * B + c.w + 1u); B += c.w;
    }
    for (int o = 16; o > 0; o >>= 1) acc += __shfl_down_sync(0xFFFFFFFFu, acc, o);
    __shared__ unsigned long long sacc[8];
    int lane = threadIdx.x & 31, w = threadIdx.x >> 5;
    if (lane == 0) sacc[w] = acc;
    __syncthreads();
    if (threadIdx.x == 0) {
        unsigned long long s = 0ull;
        #pragma unroll
        for (int k = 0; k < 8; k++) s += sacc[k];
        g_sum[b] = s;
    }
}

__global__ void finalize_kernel(float* __restrict__ out) {
    __shared__ double aucs[NSAMP];
    int b = threadIdx.x;
    if (b < NSAMP) {
        double np = (double)g_npos[b];
        double nn = (double)NPER - np;
        double spr = 0.5 * (double)g_sum[b];
        aucs[b] = (spr - np * (np + 1.0) * 0.5) / (np * nn);
    }
    __syncthreads();
    if (b == 0) {
        double tot = 0.0;
        for (int k = 0; k < NSAMP; k++) tot += aucs[k];
        out[0] = (float)(tot / (double)NSAMP);
    }
}

extern "C" void kernel_launch(void* const* d_in, const int* in_sizes, int n_in,
                              void* d_out, int out_size) {
    const float* pred  = (const float*)d_in[0];
    const int*   truem = (const int*)d_in[1];
    float*       out   = (float*)d_out;
    cudaStream_t st = 0;

    uint32_t* cnt;
    cudaGetSymbolAddress((void**)&cnt, g_cnt);

    const int TPB = 256;
    const int GRID_ALL  = NTOT / TPB;                 // 65536
    const int GRID_HALF = (NSAMP * HPER) / TPB;       // 32768

    init_kernel<<<1, 64, 0, st>>>();
    cudaMemsetAsync(cnt, 0, (size_t)CNT_TOTAL * 4, st);
    t8_hist_kernel<<<NTOT / 32768, 1024, 0, st>>>(truem, pred);

    keys_hist_kernel<<<GRID_HALF, TPB, 0, st>>>();
    scanA_kernel<<<NCHUNK2, 256, 0, st>>>();
    scanB_kernel<<<NCHUNK2 / 256, 256, 0, st>>>();

    // round 2 first: scatter then rank while records are L2-hot
    scatter_kernel<1><<<GRID_HALF, TPB, 0, st>>>();
    rank1_kernel<<<GRID_ALL, TPB, 0, st>>>();         // lam[i] = t8[r2[i]]

    // round 1: scatter then rank (reads lam, builds HPOS)
    scatter_kernel<0><<<GRID_HALF, TPB, 0, st>>>();
    rank0_kernel<<<NTOT / 16384, 1024, 0, st>>>(pred);

    auc_scan_kernel<<<NSAMP, 256, 0, st>>>();
    finalize_kernel<<<1, 64, 0, st>>>(out);
}